// round 2
// baseline (speedup 1.0000x reference)
#include <cuda_runtime.h>
#include <math.h>

// Problem constants (fixed shapes)
#define Nn 8192
#define Ee 131072
#define Cc 64
#define NELn 10
#define NBn 8
#define Gg 32
#define Hh 16
#define RMAXf 5.0f
#define AVGf 16.0f

// Scratch (device globals; no dynamic allocation allowed)
__device__ float g_h0[Nn * Cc];
__device__ int   g_elem[Nn];
__device__ float g_A[Nn * 4 * Cc];
__device__ float g_A2[Nn * 4 * Cc];
__device__ float g_out0[Nn * Cc];
__device__ float g_out1[Nn * 3 * Cc];
__device__ float g_d1[Nn * 3];

// ---------------------------------------------------------------------------
// Kernel 0: zero the aggregation buffers and the per-graph totals region of
// d_out (d_out is poisoned to 0xAA before timing).
// ---------------------------------------------------------------------------
__global__ void k_zero(float* __restrict__ out_tot) {
    int i = blockIdx.x * blockDim.x + threadIdx.x;
    int stride = gridDim.x * blockDim.x;
    const int tot = Nn * 4 * Cc;
    for (int j = i; j < tot; j += stride) {
        g_A[j]  = 0.0f;
        g_A2[j] = 0.0f;
    }
    if (i < Gg * 3) out_tot[i] = 0.0f;
}

// ---------------------------------------------------------------------------
// Kernel 1: h0 = node_attrs @ W_embed ; elem = argmax(node_attrs) (one-hot)
// grid = N blocks, 64 threads
// ---------------------------------------------------------------------------
__global__ void k_h0(const float* __restrict__ na, const float* __restrict__ We) {
    int n = blockIdx.x;
    int c = threadIdx.x;
    float acc = 0.0f;
#pragma unroll
    for (int k = 0; k < NELn; k++)
        acc = fmaf(na[n * NELn + k], We[k * Cc + c], acc);
    g_h0[n * Cc + c] = acc;
    if (c == 0) {
        int best = 0;
        float bv = na[n * NELn];
#pragma unroll
        for (int k = 1; k < NELn; k++) {
            float v = na[n * NELn + k];
            if (v > bv) { bv = v; best = k; }
        }
        g_elem[n] = best;
    }
}

// ---------------------------------------------------------------------------
// Edge kernel (both message-passing layers).
// One block (64 threads = channels) per edge.
// Only spherical components k=0..3 are consumed downstream (dead-code
// elimination of k>=4), so only radial blocks l=0,1 are computed.
// pass==0: feat=g_h0  -> g_A ;  pass==1: feat=g_out0 -> g_A2
// ---------------------------------------------------------------------------
__global__ void k_edge(const float* __restrict__ pos,
                       const float* __restrict__ shifts,
                       const int* __restrict__ ei,
                       const float* __restrict__ Wa,   // [NB,64]
                       const float* __restrict__ Wb,   // [64,256]
                       int pass) {
    const float* feat = pass ? g_out0 : g_h0;
    float* Aout       = pass ? g_A2   : g_A;

    int e = blockIdx.x;
    int c = threadIdx.x;
    int snd = ei[e];
    int rcv = ei[Ee + e];

    float vx = pos[rcv * 3 + 0] - pos[snd * 3 + 0] + shifts[e * 3 + 0];
    float vy = pos[rcv * 3 + 1] - pos[snd * 3 + 1] + shifts[e * 3 + 1];
    float vz = pos[rcv * 3 + 2] - pos[snd * 3 + 2] + shifts[e * 3 + 2];
    float r  = sqrtf(vx * vx + vy * vy + vz * vz + 1e-12f);
    float x  = r * (1.0f / RMAXf);
    if (x >= 1.0f) return;  // envelope == 0 -> zero contribution (uniform branch)

    // envelope: 1 - 21 x^5 + 35 x^6 - 15 x^7   (P=5)
    float x2 = x * x;
    float x4 = x2 * x2;
    float x5 = x4 * x;
    float env = 1.0f - 21.0f * x5 + 35.0f * x5 * x - 15.0f * x5 * x2;

    // radial basis -> hidden layer (per-thread channel c)
    float pref = sqrtf(2.0f / RMAXf) * env / r;
    float wphase = (3.14159265358979323846f / RMAXf) * r;
    float h = 0.0f;
#pragma unroll
    for (int nb = 0; nb < NBn; nb++) {
        float rbn = pref * sinf((float)(nb + 1) * wphase);
        h = fmaf(rbn, Wa[nb * Cc + c], h);
    }
    float hid = h / (1.0f + expf(-h));  // silu

    __shared__ float sh[Cc];
    sh[c] = hid;
    __syncthreads();

    // second layer: only output blocks l=0 (cols 0..63) and l=1 (cols 64..127)
    float w0 = 0.0f, w1 = 0.0f;
#pragma unroll
    for (int k = 0; k < Cc; k++) {
        float hh = sh[k];
        w0 = fmaf(hh, Wb[k * 256 + c], w0);
        w1 = fmaf(hh, Wb[k * 256 + Cc + c], w1);
    }

    float fs = feat[snd * Cc + c];
    const float s3 = 1.7320508075688772f;  // sqrt(3)
    float a1 = fs * w1 * s3 / r;            // Y1..3 = sqrt(3) * vec / r

    float* base = Aout + rcv * (4 * Cc);
    atomicAdd(base + c,          fs * w0);  // Y0 = 1
    atomicAdd(base + Cc + c,     a1 * vx);
    atomicAdd(base + 2 * Cc + c, a1 * vy);
    atomicAdd(base + 3 * Cc + c, a1 * vz);
}

// ---------------------------------------------------------------------------
// Node layer 1 (fused): h1 (k=0..3), polynomial gates, sc1, out0, out1, d1.
// grid = N blocks, 64 threads (thread = output channel d)
// ---------------------------------------------------------------------------
__global__ void k_node1(const float* __restrict__ Wmix1,   // [4,C,C] (uses l=0,1)
                        const float* __restrict__ Wsc1,    // [NEL,C,C]
                        const float* __restrict__ Wps,     // [3,NEL,C]
                        const float* __restrict__ Wpv,     // [3,NEL,C]
                        const float* __restrict__ Wp10,    // [C,C]
                        const float* __restrict__ Wp11,    // [C,C]
                        const float* __restrict__ wread1)  // [C]
{
    int n = blockIdx.x;
    int d = threadIdx.x;
    __shared__ float Ar[4][Cc];
    __shared__ float h0s[Cc];
    __shared__ float m0s[Cc];
    __shared__ float tm[3][Cc];
    __shared__ float red[3][2];

    const float ia = 1.0f / AVGf;
#pragma unroll
    for (int k = 0; k < 4; k++) Ar[k][d] = g_A[n * 256 + k * Cc + d] * ia;
    h0s[d] = g_h0[n * Cc + d];
    __syncthreads();

    float h1k[4];
#pragma unroll
    for (int k = 0; k < 4; k++) {
        const float* Wm = Wmix1 + (k == 0 ? 0 : Cc * Cc);  // L_OF[0..3] = 0,1,1,1
        float acc = 0.0f;
#pragma unroll
        for (int c = 0; c < Cc; c++) acc = fmaf(Ar[k][c], Wm[c * Cc + d], acc);
        h1k[k] = acc;
    }

    int el = g_elem[n];
    float s = h1k[0];
    float ws0 = Wps[el * Cc + d], ws1 = Wps[NELn * Cc + el * Cc + d], ws2 = Wps[2 * NELn * Cc + el * Cc + d];
    float wv0 = Wpv[el * Cc + d], wv1 = Wpv[NELn * Cc + el * Cc + d], wv2 = Wpv[2 * NELn * Cc + el * Cc + d];
    float m0 = s * (ws0 + s * (ws1 + s * ws2));  // ws0*s + ws1*s^2 + ws2*s^3
    float gv = wv0 + s * (wv1 + s * wv2);        // wv0 + wv1*s + wv2*s^2
    m0s[d] = m0;
#pragma unroll
    for (int m = 0; m < 3; m++) tm[m][d] = h1k[m + 1] * gv;
    __syncthreads();

    // out0 = m0 @ Wp1_0 + h0 @ Wsc1[el]
    float o0 = 0.0f;
    const float* Ws = Wsc1 + el * Cc * Cc;
#pragma unroll
    for (int c = 0; c < Cc; c++) o0 = fmaf(h0s[c], Ws[c * Cc + d], o0);
#pragma unroll
    for (int c = 0; c < Cc; c++) o0 = fmaf(m0s[c], Wp10[c * Cc + d], o0);
    g_out0[n * Cc + d] = o0;

    float wr = wread1[d];
#pragma unroll
    for (int m = 0; m < 3; m++) {
        float acc = 0.0f;
#pragma unroll
        for (int c = 0; c < Cc; c++) acc = fmaf(tm[m][c], Wp11[c * Cc + d], acc);
        g_out1[(n * 3 + m) * Cc + d] = acc;
        float v = acc * wr;
        v += __shfl_down_sync(0xffffffffu, v, 16);
        v += __shfl_down_sync(0xffffffffu, v, 8);
        v += __shfl_down_sync(0xffffffffu, v, 4);
        v += __shfl_down_sync(0xffffffffu, v, 2);
        v += __shfl_down_sync(0xffffffffu, v, 1);
        if ((d & 31) == 0) red[m][d >> 5] = v;
    }
    __syncthreads();
    if (d < 3) g_d1[n * 3 + d] = red[d][0] + red[d][1];
}

// ---------------------------------------------------------------------------
// Node layer 2 (fused): h2, gates, sc2, out2, vh, gate-MLP, dipoles, totals.
// grid = N blocks, 64 threads
// ---------------------------------------------------------------------------
__global__ void k_node2(const float* __restrict__ Wmix2,
                        const float* __restrict__ Wsc2,
                        const float* __restrict__ Wprod2,
                        const float* __restrict__ Wp2,
                        const float* __restrict__ Wv,      // [C,H]
                        const float* __restrict__ Wg1,     // [H,H]
                        const float* __restrict__ bg1,
                        const float* __restrict__ Wg2,
                        const float* __restrict__ bg2,
                        const float* __restrict__ wread2,
                        const int* __restrict__ batch,
                        const float* __restrict__ charges,
                        const float* __restrict__ pos,
                        float* __restrict__ out)
{
    int n = blockIdx.x;
    int d = threadIdx.x;
    __shared__ float Ar[4][Cc];
    __shared__ float o1s[3][Cc];
    __shared__ float tm[3][Cc];
    __shared__ float o2s[3][Cc];
    __shared__ float vhs[3][Hh];
    __shared__ float invs[Hh];
    __shared__ float g1s[Hh];
    __shared__ float af[Hh];

    const float ia = 1.0f / AVGf;
#pragma unroll
    for (int k = 0; k < 4; k++) Ar[k][d] = g_A2[n * 256 + k * Cc + d] * ia;
#pragma unroll
    for (int m = 0; m < 3; m++) o1s[m][d] = g_out1[(n * 3 + m) * Cc + d];
    __syncthreads();

    float h2k[4];
#pragma unroll
    for (int k = 0; k < 4; k++) {
        const float* Wm = Wmix2 + (k == 0 ? 0 : Cc * Cc);
        float acc = 0.0f;
#pragma unroll
        for (int c = 0; c < Cc; c++) acc = fmaf(Ar[k][c], Wm[c * Cc + d], acc);
        h2k[k] = acc;
    }

    int el = g_elem[n];
    float s2 = h2k[0];
    float wv0 = Wprod2[el * Cc + d], wv1 = Wprod2[NELn * Cc + el * Cc + d], wv2 = Wprod2[2 * NELn * Cc + el * Cc + d];
    float gv2 = wv0 + s2 * (wv1 + s2 * wv2);
#pragma unroll
    for (int m = 0; m < 3; m++) tm[m][d] = h2k[m + 1] * gv2;
    __syncthreads();

    const float* Ws = Wsc2 + el * Cc * Cc;
#pragma unroll
    for (int m = 0; m < 3; m++) {
        float acc = 0.0f;
#pragma unroll
        for (int c = 0; c < Cc; c++) acc = fmaf(o1s[m][c], Ws[c * Cc + d], acc);
#pragma unroll
        for (int c = 0; c < Cc; c++) acc = fmaf(tm[m][c], Wp2[c * Cc + d], acc);
        o2s[m][d] = acc;
    }
    __syncthreads();

    // vh[m][h] = out2[m] @ Wv  (48 outputs)
    if (d < 48) {
        int m = d >> 4, h = d & 15;
        float acc = 0.0f;
#pragma unroll
        for (int c = 0; c < Cc; c++) acc = fmaf(o2s[m][c], Wv[c * Hh + h], acc);
        vhs[m][h] = acc;
    }
    __syncthreads();

    if (d < Hh) {
        float v0 = vhs[0][d], v1 = vhs[1][d], v2 = vhs[2][d];
        invs[d] = sqrtf(v0 * v0 + v1 * v1 + v2 * v2 + 1e-12f);
    }
    __syncthreads();

    if (d < Hh) {
        float pre = bg1[d];
#pragma unroll
        for (int h = 0; h < Hh; h++) pre = fmaf(invs[h], Wg1[h * Hh + d], pre);
        g1s[d] = pre / (1.0f + expf(-pre));  // silu
    }
    __syncthreads();

    if (d < Hh) {
        float a = bg2[d];
#pragma unroll
        for (int h = 0; h < Hh; h++) a = fmaf(g1s[h], Wg2[h * Hh + d], a);
        af[d] = a * wread2[d];
    }
    __syncthreads();

    if (d < 3) {
        float d2 = 0.0f;
#pragma unroll
        for (int h = 0; h < Hh; h++) d2 = fmaf(vhs[d][h], af[h], d2);
        float dip = g_d1[n * 3 + d] + d2;
        out[Gg * 3 + n * 3 + d] = dip;                 // atomic_dipoles [N,3]
        int g = batch[n];
        atomicAdd(&out[g * 3 + d], dip + charges[n] * pos[n * 3 + d]);  // total [G,3]
    }
}

// ---------------------------------------------------------------------------
// Host launcher
// ---------------------------------------------------------------------------
extern "C" void kernel_launch(void* const* d_in, const int* in_sizes, int n_in,
                              void* d_out, int out_size) {
    // Locate edge_index by its unique element count (2*E) to disambiguate
    // metadata ordering (setup_inputs dict order vs reference signature order).
    int iei = -1;
    for (int i = 0; i < n_in; i++) {
        if (in_sizes[i] == 2 * Ee) { iei = i; break; }
    }
    if (iei < 0) iei = 4;  // fallback: dict order

    const float* na      = (const float*)d_in[0];
    const float* pos     = (const float*)d_in[1];
    const float* shifts  = (const float*)d_in[2];
    const float* charges = (const float*)d_in[3];
    const int*   ei      = (const int*)d_in[iei];
    const int*   batch   = (const int*)d_in[iei + 1];

    int w;
    if (iei == 4) {
        // dict order: [na,pos,shifts,charges,ei,batch,(num_graphs?),W_embed,...]
        w = (n_in > 6 && in_sizes[6] == 1) ? 7 : 6;
    } else {
        // signature order: weights start right after charges
        w = 4;
    }

    const float* W_embed = (const float*)d_in[w + 0];
    const float* Wr1a    = (const float*)d_in[w + 1];
    const float* Wr1b    = (const float*)d_in[w + 2];
    const float* Wmix1   = (const float*)d_in[w + 3];
    const float* Wsc1    = (const float*)d_in[w + 4];
    const float* Wp1s    = (const float*)d_in[w + 5];
    const float* Wp1v    = (const float*)d_in[w + 6];
    const float* Wp10    = (const float*)d_in[w + 7];
    const float* Wp11    = (const float*)d_in[w + 8];
    const float* wread1  = (const float*)d_in[w + 9];
    const float* Wr2a    = (const float*)d_in[w + 10];
    const float* Wr2b    = (const float*)d_in[w + 11];
    const float* Wmix2   = (const float*)d_in[w + 12];
    const float* Wsc2    = (const float*)d_in[w + 13];
    const float* Wprod2  = (const float*)d_in[w + 14];
    const float* Wp2     = (const float*)d_in[w + 15];
    const float* Wv      = (const float*)d_in[w + 16];
    const float* Wg1     = (const float*)d_in[w + 17];
    const float* bg1     = (const float*)d_in[w + 18];
    const float* Wg2     = (const float*)d_in[w + 19];
    const float* bg2     = (const float*)d_in[w + 20];
    const float* wread2  = (const float*)d_in[w + 21];

    float* out = (float*)d_out;

    k_zero<<<2048, 256>>>(out);
    k_h0<<<Nn, Cc>>>(na, W_embed);
    k_edge<<<Ee, Cc>>>(pos, shifts, ei, Wr1a, Wr1b, 0);
    k_node1<<<Nn, Cc>>>(Wmix1, Wsc1, Wp1s, Wp1v, Wp10, Wp11, wread1);
    k_edge<<<Ee, Cc>>>(pos, shifts, ei, Wr2a, Wr2b, 1);
    k_node2<<<Nn, Cc>>>(Wmix2, Wsc2, Wprod2, Wp2, Wv, Wg1, bg1, Wg2, bg2,
                        wread2, batch, charges, pos, out);
}

// round 3
// speedup vs baseline: 2.0886x; 2.0886x over previous
#include <cuda_runtime.h>
#include <math.h>

// Problem constants (fixed shapes)
#define Nn 8192
#define Ee 131072
#define Cc 64
#define NELn 10
#define NBn 8
#define Gg 32
#define Hh 16
#define RMAXf 5.0f
#define AVGf 16.0f
#define TBINS 8192

// Scratch (device globals; no dynamic allocation allowed)
__device__ float g_h0[Nn * Cc];
__device__ int   g_elem[Nn];
__device__ float g_A[Nn * 4 * Cc];
__device__ float g_A2[Nn * 4 * Cc];
__device__ float g_out0[Nn * Cc];
__device__ float g_out1[Nn * 3 * Cc];
__device__ float g_d1[Nn * 3];
// Radial-MLP lookup tables: w(r) for pass 1 / pass 2; 128 outputs per bin
// (cols 0..63 = l0 block, 64..127 = l1 block). Row TBINS is r=RMAX (env=0).
__device__ float g_tab1[(TBINS + 8) * 128];
__device__ float g_tab2[(TBINS + 8) * 128];

// ---------------------------------------------------------------------------
// Kernel 0: zero aggregation buffers and per-graph totals in d_out.
// ---------------------------------------------------------------------------
__global__ void k_zero(float* __restrict__ out_tot) {
    int i = blockIdx.x * blockDim.x + threadIdx.x;
    int stride = gridDim.x * blockDim.x;
    const int tot = Nn * 4 * Cc;
    for (int j = i; j < tot; j += stride) {
        g_A[j]  = 0.0f;
        g_A2[j] = 0.0f;
    }
    if (i < Gg * 3) out_tot[i] = 0.0f;
}

// ---------------------------------------------------------------------------
// Kernel 1: h0 = node_attrs @ W_embed ; elem = argmax(node_attrs) (one-hot)
// ---------------------------------------------------------------------------
__global__ void k_h0(const float* __restrict__ na, const float* __restrict__ We) {
    int n = blockIdx.x;
    int c = threadIdx.x;
    float acc = 0.0f;
#pragma unroll
    for (int k = 0; k < NELn; k++)
        acc = fmaf(na[n * NELn + k], We[k * Cc + c], acc);
    g_h0[n * Cc + c] = acc;
    if (c == 0) {
        int best = 0;
        float bv = na[n * NELn];
#pragma unroll
        for (int k = 1; k < NELn; k++) {
            float v = na[n * NELn + k];
            if (v > bv) { bv = v; best = k; }
        }
        g_elem[n] = best;
    }
}

// ---------------------------------------------------------------------------
// Radial-MLP lookup-table build. The per-edge MLP output
//   w(r) = silu(rb(r) @ Wa) @ Wb[:, 0:128]
// is a smooth function of r only -> tabulate on TBINS+1 points over [0,RMAX]
// for linear interpolation. grid = (TBINS+1, 2 passes), block = 128.
// ---------------------------------------------------------------------------
__global__ void k_table(const float* __restrict__ Wa1, const float* __restrict__ Wb1,
                        const float* __restrict__ Wa2, const float* __restrict__ Wb2) {
    int bin  = blockIdx.x;               // 0..TBINS
    int pass = blockIdx.y;               // 0 / 1
    const float* Wa = pass ? Wa2 : Wa1;
    const float* Wb = pass ? Wb2 : Wb1;
    float* tab      = pass ? g_tab2 : g_tab1;
    int c = threadIdx.x;                 // 0..127 (output column)

    float r = fmaxf((float)bin * (RMAXf / (float)TBINS), 1e-6f);
    float x = r * (1.0f / RMAXf);

    // envelope: 1 - 21 x^5 + 35 x^6 - 15 x^7 (P=5), zero at/after x=1
    float x2 = x * x;
    float x5 = x2 * x2 * x;
    float env = 1.0f - 21.0f * x5 + 35.0f * x5 * x - 15.0f * x5 * x2;
    if (x >= 1.0f) env = 0.0f;

    float pref = sqrtf(2.0f / RMAXf) * env / r;
    float wphase = (3.14159265358979323846f / RMAXf) * r;

    __shared__ float hid[Cc];
    if (c < Cc) {
        float h = 0.0f;
#pragma unroll
        for (int nb = 0; nb < NBn; nb++) {
            float rbn = pref * sinf((float)(nb + 1) * wphase);
            h = fmaf(rbn, Wa[nb * Cc + c], h);
        }
        hid[c] = h / (1.0f + expf(-h));  // silu
    }
    __syncthreads();

    float acc = 0.0f;
#pragma unroll
    for (int k = 0; k < Cc; k++)
        acc = fmaf(hid[k], Wb[k * 256 + c], acc);
    tab[bin * 128 + c] = acc;
}

// ---------------------------------------------------------------------------
// Edge kernel (both message-passing layers), warp-per-edge.
// Lane handles channels c and c+32. Radial weights come from the lerp table.
// Only spherical components k=0..3 are consumed downstream (DCE of k>=4).
// ---------------------------------------------------------------------------
__global__ void k_edge(const float* __restrict__ pos,
                       const float* __restrict__ shifts,
                       const int* __restrict__ ei,
                       int pass) {
    int gw = (blockIdx.x * blockDim.x + threadIdx.x) >> 5;   // edge id
    int lane = threadIdx.x & 31;
    if (gw >= Ee) return;

    const float* feat = pass ? g_out0 : g_h0;
    const float* tab  = pass ? g_tab2 : g_tab1;
    float* Aout       = pass ? g_A2   : g_A;

    int snd = ei[gw];
    int rcv = ei[Ee + gw];

    float vx = pos[rcv * 3 + 0] - pos[snd * 3 + 0] + shifts[gw * 3 + 0];
    float vy = pos[rcv * 3 + 1] - pos[snd * 3 + 1] + shifts[gw * 3 + 1];
    float vz = pos[rcv * 3 + 2] - pos[snd * 3 + 2] + shifts[gw * 3 + 2];
    float r  = sqrtf(vx * vx + vy * vy + vz * vz + 1e-12f);
    if (r >= RMAXf) return;  // envelope == 0 (warp-uniform branch)

    float t = r * ((float)TBINS / RMAXf);
    int   i = (int)t;
    float f = t - (float)i;
    const float* row = tab + i * 128;

    int c0 = lane, c1 = lane + 32;
    float w0a = row[c0]       + (row[128 + c0]       - row[c0])       * f;
    float w0b = row[c1]       + (row[128 + c1]       - row[c1])       * f;
    float w1a = row[c0 + 64]  + (row[192 + c0]       - row[c0 + 64])  * f;
    float w1b = row[c1 + 64]  + (row[192 + c1]       - row[c1 + 64])  * f;

    float fsa = feat[snd * Cc + c0];
    float fsb = feat[snd * Cc + c1];

    const float s3 = 1.7320508075688772f;   // sqrt(3)
    float irs = s3 / r;
    float ga = fsa * w1a * irs;
    float gb = fsb * w1b * irs;

    float* base = Aout + rcv * (4 * Cc);
    atomicAdd(base + c0,            fsa * w0a);   // Y0 = 1
    atomicAdd(base + c1,            fsb * w0b);
    atomicAdd(base + Cc + c0,       ga * vx);     // Y1..3 = sqrt(3)*vec/r
    atomicAdd(base + Cc + c1,       gb * vx);
    atomicAdd(base + 2 * Cc + c0,   ga * vy);
    atomicAdd(base + 2 * Cc + c1,   gb * vy);
    atomicAdd(base + 3 * Cc + c0,   ga * vz);
    atomicAdd(base + 3 * Cc + c1,   gb * vz);
}

// ---------------------------------------------------------------------------
// Node layer 1 (fused): h1 (k=0..3), polynomial gates, sc1, out0, out1, d1.
// ---------------------------------------------------------------------------
__global__ void k_node1(const float* __restrict__ Wmix1,
                        const float* __restrict__ Wsc1,
                        const float* __restrict__ Wps,
                        const float* __restrict__ Wpv,
                        const float* __restrict__ Wp10,
                        const float* __restrict__ Wp11,
                        const float* __restrict__ wread1)
{
    int n = blockIdx.x;
    int d = threadIdx.x;
    __shared__ float Ar[4][Cc];
    __shared__ float h0s[Cc];
    __shared__ float m0s[Cc];
    __shared__ float tm[3][Cc];
    __shared__ float red[3][2];

    const float ia = 1.0f / AVGf;
#pragma unroll
    for (int k = 0; k < 4; k++) Ar[k][d] = g_A[n * 256 + k * Cc + d] * ia;
    h0s[d] = g_h0[n * Cc + d];
    __syncthreads();

    float h1k[4];
#pragma unroll
    for (int k = 0; k < 4; k++) {
        const float* Wm = Wmix1 + (k == 0 ? 0 : Cc * Cc);  // L_OF[0..3]=0,1,1,1
        float acc = 0.0f;
#pragma unroll
        for (int c = 0; c < Cc; c++) acc = fmaf(Ar[k][c], Wm[c * Cc + d], acc);
        h1k[k] = acc;
    }

    int el = g_elem[n];
    float s = h1k[0];
    float ws0 = Wps[el * Cc + d], ws1 = Wps[NELn * Cc + el * Cc + d], ws2 = Wps[2 * NELn * Cc + el * Cc + d];
    float wv0 = Wpv[el * Cc + d], wv1 = Wpv[NELn * Cc + el * Cc + d], wv2 = Wpv[2 * NELn * Cc + el * Cc + d];
    float m0 = s * (ws0 + s * (ws1 + s * ws2));
    float gv = wv0 + s * (wv1 + s * wv2);
    m0s[d] = m0;
#pragma unroll
    for (int m = 0; m < 3; m++) tm[m][d] = h1k[m + 1] * gv;
    __syncthreads();

    float o0 = 0.0f;
    const float* Ws = Wsc1 + el * Cc * Cc;
#pragma unroll
    for (int c = 0; c < Cc; c++) o0 = fmaf(h0s[c], Ws[c * Cc + d], o0);
#pragma unroll
    for (int c = 0; c < Cc; c++) o0 = fmaf(m0s[c], Wp10[c * Cc + d], o0);
    g_out0[n * Cc + d] = o0;

    float wr = wread1[d];
#pragma unroll
    for (int m = 0; m < 3; m++) {
        float acc = 0.0f;
#pragma unroll
        for (int c = 0; c < Cc; c++) acc = fmaf(tm[m][c], Wp11[c * Cc + d], acc);
        g_out1[(n * 3 + m) * Cc + d] = acc;
        float v = acc * wr;
        v += __shfl_down_sync(0xffffffffu, v, 16);
        v += __shfl_down_sync(0xffffffffu, v, 8);
        v += __shfl_down_sync(0xffffffffu, v, 4);
        v += __shfl_down_sync(0xffffffffu, v, 2);
        v += __shfl_down_sync(0xffffffffu, v, 1);
        if ((d & 31) == 0) red[m][d >> 5] = v;
    }
    __syncthreads();
    if (d < 3) g_d1[n * 3 + d] = red[d][0] + red[d][1];
}

// ---------------------------------------------------------------------------
// Node layer 2 (fused): h2, gates, sc2, out2, vh, gate-MLP, dipoles, totals.
// ---------------------------------------------------------------------------
__global__ void k_node2(const float* __restrict__ Wmix2,
                        const float* __restrict__ Wsc2,
                        const float* __restrict__ Wprod2,
                        const float* __restrict__ Wp2,
                        const float* __restrict__ Wv,
                        const float* __restrict__ Wg1,
                        const float* __restrict__ bg1,
                        const float* __restrict__ Wg2,
                        const float* __restrict__ bg2,
                        const float* __restrict__ wread2,
                        const int* __restrict__ batch,
                        const float* __restrict__ charges,
                        const float* __restrict__ pos,
                        float* __restrict__ out)
{
    int n = blockIdx.x;
    int d = threadIdx.x;
    __shared__ float Ar[4][Cc];
    __shared__ float o1s[3][Cc];
    __shared__ float tm[3][Cc];
    __shared__ float o2s[3][Cc];
    __shared__ float vhs[3][Hh];
    __shared__ float invs[Hh];
    __shared__ float g1s[Hh];
    __shared__ float af[Hh];

    const float ia = 1.0f / AVGf;
#pragma unroll
    for (int k = 0; k < 4; k++) Ar[k][d] = g_A2[n * 256 + k * Cc + d] * ia;
#pragma unroll
    for (int m = 0; m < 3; m++) o1s[m][d] = g_out1[(n * 3 + m) * Cc + d];
    __syncthreads();

    float h2k[4];
#pragma unroll
    for (int k = 0; k < 4; k++) {
        const float* Wm = Wmix2 + (k == 0 ? 0 : Cc * Cc);
        float acc = 0.0f;
#pragma unroll
        for (int c = 0; c < Cc; c++) acc = fmaf(Ar[k][c], Wm[c * Cc + d], acc);
        h2k[k] = acc;
    }

    int el = g_elem[n];
    float s2 = h2k[0];
    float wv0 = Wprod2[el * Cc + d], wv1 = Wprod2[NELn * Cc + el * Cc + d], wv2 = Wprod2[2 * NELn * Cc + el * Cc + d];
    float gv2 = wv0 + s2 * (wv1 + s2 * wv2);
#pragma unroll
    for (int m = 0; m < 3; m++) tm[m][d] = h2k[m + 1] * gv2;
    __syncthreads();

    const float* Ws = Wsc2 + el * Cc * Cc;
#pragma unroll
    for (int m = 0; m < 3; m++) {
        float acc = 0.0f;
#pragma unroll
        for (int c = 0; c < Cc; c++) acc = fmaf(o1s[m][c], Ws[c * Cc + d], acc);
#pragma unroll
        for (int c = 0; c < Cc; c++) acc = fmaf(tm[m][c], Wp2[c * Cc + d], acc);
        o2s[m][d] = acc;
    }
    __syncthreads();

    if (d < 48) {
        int m = d >> 4, h = d & 15;
        float acc = 0.0f;
#pragma unroll
        for (int c = 0; c < Cc; c++) acc = fmaf(o2s[m][c], Wv[c * Hh + h], acc);
        vhs[m][h] = acc;
    }
    __syncthreads();

    if (d < Hh) {
        float v0 = vhs[0][d], v1 = vhs[1][d], v2 = vhs[2][d];
        invs[d] = sqrtf(v0 * v0 + v1 * v1 + v2 * v2 + 1e-12f);
    }
    __syncthreads();

    if (d < Hh) {
        float pre = bg1[d];
#pragma unroll
        for (int h = 0; h < Hh; h++) pre = fmaf(invs[h], Wg1[h * Hh + d], pre);
        g1s[d] = pre / (1.0f + expf(-pre));
    }
    __syncthreads();

    if (d < Hh) {
        float a = bg2[d];
#pragma unroll
        for (int h = 0; h < Hh; h++) a = fmaf(g1s[h], Wg2[h * Hh + d], a);
        af[d] = a * wread2[d];
    }
    __syncthreads();

    if (d < 3) {
        float d2 = 0.0f;
#pragma unroll
        for (int h = 0; h < Hh; h++) d2 = fmaf(vhs[d][h], af[h], d2);
        float dip = g_d1[n * 3 + d] + d2;
        out[Gg * 3 + n * 3 + d] = dip;
        int g = batch[n];
        atomicAdd(&out[g * 3 + d], dip + charges[n] * pos[n * 3 + d]);
    }
}

// ---------------------------------------------------------------------------
// Host launcher
// ---------------------------------------------------------------------------
extern "C" void kernel_launch(void* const* d_in, const int* in_sizes, int n_in,
                              void* d_out, int out_size) {
    int iei = -1;
    for (int i = 0; i < n_in; i++) {
        if (in_sizes[i] == 2 * Ee) { iei = i; break; }
    }
    if (iei < 0) iei = 4;

    const float* na      = (const float*)d_in[0];
    const float* pos     = (const float*)d_in[1];
    const float* shifts  = (const float*)d_in[2];
    const float* charges = (const float*)d_in[3];
    const int*   ei      = (const int*)d_in[iei];
    const int*   batch   = (const int*)d_in[iei + 1];

    int w;
    if (iei == 4) {
        w = (n_in > 6 && in_sizes[6] == 1) ? 7 : 6;
    } else {
        w = 4;
    }

    const float* W_embed = (const float*)d_in[w + 0];
    const float* Wr1a    = (const float*)d_in[w + 1];
    const float* Wr1b    = (const float*)d_in[w + 2];
    const float* Wmix1   = (const float*)d_in[w + 3];
    const float* Wsc1    = (const float*)d_in[w + 4];
    const float* Wp1s    = (const float*)d_in[w + 5];
    const float* Wp1v    = (const float*)d_in[w + 6];
    const float* Wp10    = (const float*)d_in[w + 7];
    const float* Wp11    = (const float*)d_in[w + 8];
    const float* wread1  = (const float*)d_in[w + 9];
    const float* Wr2a    = (const float*)d_in[w + 10];
    const float* Wr2b    = (const float*)d_in[w + 11];
    const float* Wmix2   = (const float*)d_in[w + 12];
    const float* Wsc2    = (const float*)d_in[w + 13];
    const float* Wprod2  = (const float*)d_in[w + 14];
    const float* Wp2     = (const float*)d_in[w + 15];
    const float* Wv      = (const float*)d_in[w + 16];
    const float* Wg1     = (const float*)d_in[w + 17];
    const float* bg1     = (const float*)d_in[w + 18];
    const float* Wg2     = (const float*)d_in[w + 19];
    const float* bg2     = (const float*)d_in[w + 20];
    const float* wread2  = (const float*)d_in[w + 21];

    float* out = (float*)d_out;

    k_zero<<<2048, 256>>>(out);
    k_h0<<<Nn, Cc>>>(na, W_embed);
    dim3 tg(TBINS + 1, 2);
    k_table<<<tg, 128>>>(Wr1a, Wr1b, Wr2a, Wr2b);
    k_edge<<<Ee / 8, 256>>>(pos, shifts, ei, 0);
    k_node1<<<Nn, Cc>>>(Wmix1, Wsc1, Wp1s, Wp1v, Wp10, Wp11, wread1);
    k_edge<<<Ee / 8, 256>>>(pos, shifts, ei, 1);
    k_node2<<<Nn, Cc>>>(Wmix2, Wsc2, Wprod2, Wp2, Wv, Wg1, bg1, Wg2, bg2,
                        wread2, batch, charges, pos, out);
}